// round 5
// baseline (speedup 1.0000x reference)
#include <cuda_runtime.h>

#define B_    32
#define C_    256
#define L_    336
#define O_    96
#define KC_   4
#define NL_   2
#define DFF_  1024
#define PROWS 268              // per-cluster channel list padded to multiples of 4
#define NGRP  67               // PROWS / 4 channel-groups -> 128-row GEMM tiles
#define MTOT  (PROWS * 32)     // 8576 padded rows (prow*32 + b)

// ------------------------- device scratch -------------------------
__device__ float g_Z[(size_t)MTOT * L_];     // normalized / residual stream
__device__ float g_H[(size_t)MTOT * DFF_];   // hidden activations
__device__ float g_mean[MTOT];
__device__ float g_std[MTOT];
__device__ int   g_chan[PROWS];              // channel id or -1 (pad)
__device__ int   g_clusprow[PROWS];          // cluster of each prow
__device__ int   g_clusgrp[NGRP];            // cluster of each 4-channel group

// ------------------------- f32x2 helpers (Blackwell packed fp32) ---
__device__ __forceinline__ unsigned long long fma2(unsigned long long a,
                                                   unsigned long long b,
                                                   unsigned long long c) {
    unsigned long long d;
    asm("fma.rn.f32x2 %0, %1, %2, %3;" : "=l"(d) : "l"(a), "l"(b), "l"(c));
    return d;
}
__device__ __forceinline__ unsigned long long dup2(float a) {
    unsigned long long d;
    unsigned int ai = __float_as_uint(a);
    asm("mov.b64 %0, {%1, %1};" : "=l"(d) : "r"(ai));
    return d;
}
__device__ __forceinline__ void unpack2(unsigned long long v, float& lo, float& hi) {
    unsigned int a, b;
    asm("mov.b64 {%0, %1}, %2;" : "=r"(a), "=r"(b) : "l"(v));
    lo = __uint_as_float(a);
    hi = __uint_as_float(b);
}

// ------------------------- prep: bucket channels by cluster --------
__global__ void prep_kernel(const int* __restrict__ assign) {
    __shared__ int sa[C_];
    __shared__ int cnt[KC_];
    __shared__ int base[KC_ + 1];
    int t = threadIdx.x;
    if (t < KC_) cnt[t] = 0;
    __syncthreads();
    if (t < C_) {
        int k = assign[t];
        k = min(max(k, 0), KC_ - 1);
        sa[t] = k;
        atomicAdd(&cnt[k], 1);
    }
    __syncthreads();
    if (t == 0) {
        base[0] = 0;
        for (int k = 0; k < KC_; k++) base[k + 1] = base[k] + ((cnt[k] + 3) & ~3);
    }
    __syncthreads();
    for (int p = t; p < PROWS; p += blockDim.x) {
        int kk = 0;
        for (int k = 0; k < KC_; k++) if (p >= base[k + 1]) kk = k + 1;
        if (kk >= KC_) kk = 0;
        g_clusprow[p] = kk;
        g_chan[p] = -1;
    }
    __syncthreads();   // defaults visible before real channel writes
    if (t < C_) {
        int k = sa[t];
        int rank = 0;
        for (int c = 0; c < t; c++) rank += (sa[c] == k);
        g_chan[base[k] + rank] = t;
    }
    if (t < NGRP) {
        int p = t * 4;
        int kk = 0;
        for (int k = 0; k < KC_; k++) if (p >= base[k + 1]) kk = k + 1;
        if (kk >= KC_) kk = 0;
        g_clusgrp[t] = kk;
    }
}

// ------------------------- RevIN normalize (two-pass) --------------
__global__ void revin_kernel(const float* __restrict__ x,
                             const float* __restrict__ rev_w,
                             const float* __restrict__ rev_b) {
    int r = blockIdx.x;             // 0..MTOT-1
    int prow = r >> 5, b = r & 31;
    int c = g_chan[prow];
    int t = threadIdx.x;            // 128 threads
    __shared__ float sx[L_];
    __shared__ float sred[8];
    float* zr = g_Z + (size_t)r * L_;

    if (c < 0) {
        for (int i = t; i < L_; i += 128) zr[i] = 0.f;
        if (t == 0) { g_mean[r] = 0.f; g_std[r] = 1.f; }
        return;
    }
    const float* xr = x + ((size_t)b * C_ + c) * L_;
    float s = 0.f;
    for (int i = t; i < L_; i += 128) { float v = xr[i]; sx[i] = v; s += v; }
    #pragma unroll
    for (int o = 16; o > 0; o >>= 1) s += __shfl_down_sync(0xffffffffu, s, o);
    if ((t & 31) == 0) sred[t >> 5] = s;
    __syncthreads();
    if (t < 32) {
        float v = (t < 4) ? sred[t] : 0.f;
        v += __shfl_down_sync(0xffffffffu, v, 2);
        v += __shfl_down_sync(0xffffffffu, v, 1);
        if (t == 0) sred[4] = v;
    }
    __syncthreads();
    float mean = sred[4] * (1.0f / L_);

    float vs = 0.f;
    for (int i = t; i < L_; i += 128) { float d = sx[i] - mean; vs += d * d; }
    #pragma unroll
    for (int o = 16; o > 0; o >>= 1) vs += __shfl_down_sync(0xffffffffu, vs, o);
    if ((t & 31) == 0) sred[t >> 5] = vs;
    __syncthreads();
    if (t < 32) {
        float v = (t < 4) ? sred[t] : 0.f;
        v += __shfl_down_sync(0xffffffffu, v, 2);
        v += __shfl_down_sync(0xffffffffu, v, 1);
        if (t == 0) sred[5] = v;
    }
    __syncthreads();
    float var  = sred[5] * (1.0f / L_);
    float stdv = sqrtf(var + 1e-5f);
    float w  = rev_w[c], rb = rev_b[c];
    float rs = w / stdv;
    for (int i = t; i < L_; i += 128) zr[i] = (sx[i] - mean) * rs + rb;
    if (t == 0) { g_mean[r] = mean; g_std[r] = stdv; }
}

// ------------------------- fused FFN GEMMs (f32x2 SGEMM) -----------
// FFN1: H = relu(Z @ W1[k,l] + b1)      (K=336,  N=1024)
// FFN2: Z = Z + H @ W2[k,l] + b2        (K=1024, N=336, in-place residual)
template <bool FFN1>
__global__ __launch_bounds__(256, 2) void ffn_gemm(const float* __restrict__ W,
                                                   const float* __restrict__ bias,
                                                   int layer) {
    constexpr int KDIM = FFN1 ? L_ : DFF_;
    constexpr int NDIM = FFN1 ? DFF_ : L_;
    constexpr int LDA  = FFN1 ? L_ : DFF_;
    constexpr int KT   = KDIM / 8;
    const float* A    = FFN1 ? g_Z : g_H;
    float*       Cout = FFN1 ? g_H : g_Z;

    __shared__ __align__(16) float As[2][8][128];
    __shared__ __align__(16) float Bs[2][8][128];

    int tid = threadIdx.x;
    int tx = tid & 15, ty = tid >> 4;
    int m0 = blockIdx.y * 128;
    int n0 = blockIdx.x * 128;
    int kc = g_clusgrp[blockIdx.y];
    const float* Wp = W + (size_t)(kc * NL_ + layer) * KDIM * NDIM;
    const float* bp = bias + (size_t)(kc * NL_ + layer) * NDIM;

    int arow = tid >> 1, ak = (tid & 1) * 4;
    int bkr  = tid >> 5, bn = (tid & 31) * 4;
    const float* Ag = A  + (size_t)(m0 + arow) * LDA + ak;
    const float* Bg = Wp + (size_t)bkr * NDIM + n0 + bn;
    const bool bvalid = FFN1 ? true : (n0 + bn < NDIM);

    float4 aR = *(const float4*)Ag;
    float4 bR = bvalid ? *(const float4*)Bg : make_float4(0.f, 0.f, 0.f, 0.f);
    As[0][ak + 0][arow] = aR.x; As[0][ak + 1][arow] = aR.y;
    As[0][ak + 2][arow] = aR.z; As[0][ak + 3][arow] = aR.w;
    *(float4*)&Bs[0][bkr][bn] = bR;
    __syncthreads();

    unsigned long long acc[8][4];
    #pragma unroll
    for (int r = 0; r < 8; r++)
        #pragma unroll
        for (int j = 0; j < 4; j++) acc[r][j] = 0ULL;

    int buf = 0;
    #pragma unroll 1
    for (int kt = 0; kt < KT; ++kt) {
        float4 aN, bN;
        if (kt + 1 < KT) {
            aN = *(const float4*)(Ag + (kt + 1) * 8);
            bN = bvalid ? *(const float4*)(Bg + (size_t)(kt + 1) * 8 * NDIM)
                        : make_float4(0.f, 0.f, 0.f, 0.f);
        }
        #pragma unroll
        for (int kk = 0; kk < 8; kk++) {
            float4 a0 = *(const float4*)&As[buf][kk][ty * 4];
            float4 a1 = *(const float4*)&As[buf][kk][64 + ty * 4];
            ulonglong2 b0 = *(const ulonglong2*)&Bs[buf][kk][tx * 4];
            ulonglong2 b1 = *(const ulonglong2*)&Bs[buf][kk][64 + tx * 4];
            unsigned long long bv0 = b0.x, bv1 = b0.y, bv2 = b1.x, bv3 = b1.y;
            float av[8] = {a0.x, a0.y, a0.z, a0.w, a1.x, a1.y, a1.z, a1.w};
            #pragma unroll
            for (int r = 0; r < 8; r++) {
                unsigned long long ad = dup2(av[r]);
                acc[r][0] = fma2(ad, bv0, acc[r][0]);
                acc[r][1] = fma2(ad, bv1, acc[r][1]);
                acc[r][2] = fma2(ad, bv2, acc[r][2]);
                acc[r][3] = fma2(ad, bv3, acc[r][3]);
            }
        }
        if (kt + 1 < KT) {
            int nb = buf ^ 1;
            As[nb][ak + 0][arow] = aN.x; As[nb][ak + 1][arow] = aN.y;
            As[nb][ak + 2][arow] = aN.z; As[nb][ak + 3][arow] = aN.w;
            *(float4*)&Bs[nb][bkr][bn] = bN;
            __syncthreads();
            buf = nb;
        }
    }

    // epilogue
    bool cval0 = true, cval1 = true;
    if (!FFN1) {
        cval0 = (n0 + tx * 4 + 4 <= NDIM);
        cval1 = (n0 + 64 + tx * 4 + 4 <= NDIM);
    }
    float4 bias0 = make_float4(0.f, 0.f, 0.f, 0.f);
    float4 bias1 = make_float4(0.f, 0.f, 0.f, 0.f);
    if (cval0) bias0 = *(const float4*)&bp[n0 + tx * 4];
    if (cval1) bias1 = *(const float4*)&bp[n0 + 64 + tx * 4];

    #pragma unroll
    for (int r = 0; r < 8; r++) {
        int row = m0 + ((r < 4) ? (ty * 4 + r) : (64 + ty * 4 + (r - 4)));
        float p0x, p0y, p1x, p1y, p2x, p2y, p3x, p3y;
        unpack2(acc[r][0], p0x, p0y);
        unpack2(acc[r][1], p1x, p1y);
        unpack2(acc[r][2], p2x, p2y);
        unpack2(acc[r][3], p3x, p3y);
        if (FFN1) {
            float4 v0 = make_float4(fmaxf(p0x + bias0.x, 0.f), fmaxf(p0y + bias0.y, 0.f),
                                    fmaxf(p1x + bias0.z, 0.f), fmaxf(p1y + bias0.w, 0.f));
            float4 v1 = make_float4(fmaxf(p2x + bias1.x, 0.f), fmaxf(p2y + bias1.y, 0.f),
                                    fmaxf(p3x + bias1.z, 0.f), fmaxf(p3y + bias1.w, 0.f));
            *(float4*)&Cout[(size_t)row * NDIM + n0 + tx * 4] = v0;
            *(float4*)&Cout[(size_t)row * NDIM + n0 + 64 + tx * 4] = v1;
        } else {
            if (cval0) {
                float* cp = &Cout[(size_t)row * NDIM + n0 + tx * 4];
                float4 old = *(const float4*)cp;
                *(float4*)cp = make_float4(old.x + p0x + bias0.x, old.y + p0y + bias0.y,
                                           old.z + p1x + bias0.z, old.w + p1y + bias0.w);
            }
            if (cval1) {
                float* cp = &Cout[(size_t)row * NDIM + n0 + 64 + tx * 4];
                float4 old = *(const float4*)cp;
                *(float4*)cp = make_float4(old.x + p2x + bias1.x, old.y + p2y + bias1.y,
                                           old.z + p3x + bias1.z, old.w + p3y + bias1.w);
            }
        }
    }
}

// ------------------------- head + denorm + transpose ----------------
__global__ void head_kernel(const float* __restrict__ Wh,
                            const float* __restrict__ bh,
                            const float* __restrict__ rev_w,
                            const float* __restrict__ rev_b,
                            float* __restrict__ out) {
    int prow = blockIdx.x;
    int c = g_chan[prow];
    if (c < 0) return;
    int kc = g_clusprow[prow];

    __shared__ __align__(16) float Zs[32][65];
    __shared__ __align__(16) float Ws[64][96];

    int tid = threadIdx.x;       // 256
    int row = tid & 31;          // batch index b
    int cg  = tid >> 5;          // 8 column groups of 12
    float acc[12];
    #pragma unroll
    for (int j = 0; j < 12; j++) acc[j] = 0.f;

    const float* Whk = Wh + (size_t)kc * L_ * O_;
    for (int l0 = 0; l0 < L_; l0 += 64) {
        int lc = min(64, L_ - l0);
        for (int i = tid; i < 32 * 64; i += 256) {
            int rr = i >> 6, ll = i & 63;
            Zs[rr][ll] = (ll < lc) ? g_Z[(size_t)(prow * 32 + rr) * L_ + l0 + ll] : 0.f;
        }
        for (int i = tid; i < 64 * 96; i += 256) {
            int ll = i / 96, o = i - ll * 96;
            Ws[ll][o] = (ll < lc) ? Whk[(size_t)(l0 + ll) * O_ + o] : 0.f;
        }
        __syncthreads();
        #pragma unroll 8
        for (int ll = 0; ll < 64; ll++) {
            float a = Zs[row][ll];
            float4 w0 = *(const float4*)&Ws[ll][cg * 12];
            float4 w1 = *(const float4*)&Ws[ll][cg * 12 + 4];
            float4 w2 = *(const float4*)&Ws[ll][cg * 12 + 8];
            acc[0]  += a * w0.x; acc[1]  += a * w0.y; acc[2]  += a * w0.z; acc[3]  += a * w0.w;
            acc[4]  += a * w1.x; acc[5]  += a * w1.y; acc[6]  += a * w1.z; acc[7]  += a * w1.w;
            acc[8]  += a * w2.x; acc[9]  += a * w2.y; acc[10] += a * w2.z; acc[11] += a * w2.w;
        }
        __syncthreads();
    }

    int rg = prow * 32 + row;
    float mean = g_mean[rg], stdv = g_std[rg];
    float w = rev_w[c], rb = rev_b[c];
    float scale = stdv / w;
    #pragma unroll
    for (int j = 0; j < 12; j++) {
        int o = cg * 12 + j;
        float y = acc[j] + bh[kc * O_ + o];
        out[((size_t)row * O_ + o) * C_ + c] = (y - rb) * scale + mean;
    }
}

// ------------------------- launch ----------------------------------
extern "C" void kernel_launch(void* const* d_in, const int* in_sizes, int n_in,
                              void* d_out, int out_size) {
    const float* x     = (const float*)d_in[0];
    const float* rev_w = (const float*)d_in[1];
    const float* rev_b = (const float*)d_in[2];
    const float* W1    = (const float*)d_in[3];
    const float* b1    = (const float*)d_in[4];
    const float* W2    = (const float*)d_in[5];
    const float* b2    = (const float*)d_in[6];
    const float* Wh    = (const float*)d_in[7];
    const float* bh    = (const float*)d_in[8];
    const int*   assign = (const int*)d_in[9];
    float* out = (float*)d_out;

    prep_kernel<<<1, 256>>>(assign);
    revin_kernel<<<MTOT, 128>>>(x, rev_w, rev_b);
    for (int l = 0; l < NL_; l++) {
        ffn_gemm<true ><<<dim3(DFF_ / 128, NGRP), 256>>>(W1, b1, l);
        ffn_gemm<false><<<dim3((L_ + 127) / 128, NGRP), 256>>>(W2, b2, l);
    }
    head_kernel<<<PROWS, 256>>>(Wh, bh, rev_w, rev_b, out);
}

// round 6
// speedup vs baseline: 1.0016x; 1.0016x over previous
#include <cuda_runtime.h>

#define B_    32
#define C_    256
#define L_    336
#define O_    96
#define KC_   4
#define NL_   2
#define DFF_  1024
#define PROWS 268              // per-cluster channel list padded to multiples of 4
#define NGRP  67               // PROWS / 4 channel-groups -> 128-row GEMM tiles
#define MTOT  (PROWS * 32)     // 8576 padded rows (prow*32 + b)

// ------------------------- device scratch -------------------------
__device__ float g_Z[(size_t)MTOT * L_];     // normalized / residual stream
__device__ float g_H[(size_t)MTOT * DFF_];   // hidden activations
__device__ float g_mean[MTOT];
__device__ float g_std[MTOT];
__device__ int   g_chan[PROWS];              // channel id or -1 (pad)
__device__ int   g_clusprow[PROWS];          // cluster of each prow
__device__ int   g_clusgrp[NGRP];            // cluster of each 4-channel group

// ------------------------- f32x2 helpers (Blackwell packed fp32) ---
__device__ __forceinline__ unsigned long long fma2(unsigned long long a,
                                                   unsigned long long b,
                                                   unsigned long long c) {
    unsigned long long d;
    asm("fma.rn.f32x2 %0, %1, %2, %3;" : "=l"(d) : "l"(a), "l"(b), "l"(c));
    return d;
}
__device__ __forceinline__ unsigned long long dup2(float a) {
    unsigned long long d;
    unsigned int ai = __float_as_uint(a);
    asm("mov.b64 %0, {%1, %1};" : "=l"(d) : "r"(ai));
    return d;
}
__device__ __forceinline__ void unpack2(unsigned long long v, float& lo, float& hi) {
    unsigned int a, b;
    asm("mov.b64 {%0, %1}, %2;" : "=r"(a), "=r"(b) : "l"(v));
    lo = __uint_as_float(a);
    hi = __uint_as_float(b);
}

// ------------------------- prep: bucket channels by cluster --------
__global__ void prep_kernel(const int* __restrict__ assign) {
    __shared__ int sa[C_];
    __shared__ int cnt[KC_];
    __shared__ int base[KC_ + 1];
    int t = threadIdx.x;
    if (t < KC_) cnt[t] = 0;
    __syncthreads();
    if (t < C_) {
        int k = assign[t];
        k = min(max(k, 0), KC_ - 1);
        sa[t] = k;
        atomicAdd(&cnt[k], 1);
    }
    __syncthreads();
    if (t == 0) {
        base[0] = 0;
        for (int k = 0; k < KC_; k++) base[k + 1] = base[k] + ((cnt[k] + 3) & ~3);
    }
    __syncthreads();
    for (int p = t; p < PROWS; p += blockDim.x) {
        int kk = 0;
        for (int k = 0; k < KC_; k++) if (p >= base[k + 1]) kk = k + 1;
        if (kk >= KC_) kk = 0;
        g_clusprow[p] = kk;
        g_chan[p] = -1;
    }
    __syncthreads();   // defaults visible before real channel writes
    if (t < C_) {
        int k = sa[t];
        int rank = 0;
        for (int c = 0; c < t; c++) rank += (sa[c] == k);
        g_chan[base[k] + rank] = t;
    }
    if (t < NGRP) {
        int p = t * 4;
        int kk = 0;
        for (int k = 0; k < KC_; k++) if (p >= base[k + 1]) kk = k + 1;
        if (kk >= KC_) kk = 0;
        g_clusgrp[t] = kk;
    }
}

// ------------------------- RevIN normalize (two-pass) --------------
__global__ void revin_kernel(const float* __restrict__ x,
                             const float* __restrict__ rev_w,
                             const float* __restrict__ rev_b) {
    int r = blockIdx.x;             // 0..MTOT-1
    int prow = r >> 5, b = r & 31;
    int c = g_chan[prow];
    int t = threadIdx.x;            // 128 threads
    __shared__ float sx[L_];
    __shared__ float sred[8];
    float* zr = g_Z + (size_t)r * L_;

    if (c < 0) {
        for (int i = t; i < L_; i += 128) zr[i] = 0.f;
        if (t == 0) { g_mean[r] = 0.f; g_std[r] = 1.f; }
        return;
    }
    const float* xr = x + ((size_t)b * C_ + c) * L_;
    float s = 0.f;
    for (int i = t; i < L_; i += 128) { float v = xr[i]; sx[i] = v; s += v; }
    #pragma unroll
    for (int o = 16; o > 0; o >>= 1) s += __shfl_down_sync(0xffffffffu, s, o);
    if ((t & 31) == 0) sred[t >> 5] = s;
    __syncthreads();
    if (t < 32) {
        float v = (t < 4) ? sred[t] : 0.f;
        v += __shfl_down_sync(0xffffffffu, v, 2);
        v += __shfl_down_sync(0xffffffffu, v, 1);
        if (t == 0) sred[4] = v;
    }
    __syncthreads();
    float mean = sred[4] * (1.0f / L_);

    float vs = 0.f;
    for (int i = t; i < L_; i += 128) { float d = sx[i] - mean; vs += d * d; }
    #pragma unroll
    for (int o = 16; o > 0; o >>= 1) vs += __shfl_down_sync(0xffffffffu, vs, o);
    if ((t & 31) == 0) sred[t >> 5] = vs;
    __syncthreads();
    if (t < 32) {
        float v = (t < 4) ? sred[t] : 0.f;
        v += __shfl_down_sync(0xffffffffu, v, 2);
        v += __shfl_down_sync(0xffffffffu, v, 1);
        if (t == 0) sred[5] = v;
    }
    __syncthreads();
    float var  = sred[5] * (1.0f / L_);
    float stdv = sqrtf(var + 1e-5f);
    float w  = rev_w[c], rb = rev_b[c];
    float rs = w / stdv;
    for (int i = t; i < L_; i += 128) zr[i] = (sx[i] - mean) * rs + rb;
    if (t == 0) { g_mean[r] = mean; g_std[r] = stdv; }
}

// ------------------------- fused FFN GEMMs (f32x2 SGEMM) -----------
// FFN1: H = relu(Z @ W1[k,l] + b1)      (K=336,  N=1024)
// FFN2: Z = Z + H @ W2[k,l] + b2        (K=1024, N=336, in-place residual)
template <bool FFN1>
__global__ __launch_bounds__(256, 2) void ffn_gemm(const float* __restrict__ W,
                                                   const float* __restrict__ bias,
                                                   int layer) {
    constexpr int KDIM = FFN1 ? L_ : DFF_;
    constexpr int NDIM = FFN1 ? DFF_ : L_;
    constexpr int LDA  = FFN1 ? L_ : DFF_;
    constexpr int KT   = KDIM / 8;
    const float* A    = FFN1 ? g_Z : g_H;
    float*       Cout = FFN1 ? g_H : g_Z;

    __shared__ __align__(16) float As[2][8][128];
    __shared__ __align__(16) float Bs[2][8][128];

    int tid = threadIdx.x;
    int tx = tid & 15, ty = tid >> 4;
    int m0 = blockIdx.y * 128;
    int n0 = blockIdx.x * 128;
    int kc = g_clusgrp[blockIdx.y];
    const float* Wp = W + (size_t)(kc * NL_ + layer) * KDIM * NDIM;
    const float* bp = bias + (size_t)(kc * NL_ + layer) * NDIM;

    int arow = tid >> 1, ak = (tid & 1) * 4;
    int bkr  = tid >> 5, bn = (tid & 31) * 4;
    const float* Ag = A  + (size_t)(m0 + arow) * LDA + ak;
    const float* Bg = Wp + (size_t)bkr * NDIM + n0 + bn;
    const bool bvalid = FFN1 ? true : (n0 + bn < NDIM);

    float4 aR = *(const float4*)Ag;
    float4 bR = bvalid ? *(const float4*)Bg : make_float4(0.f, 0.f, 0.f, 0.f);
    As[0][ak + 0][arow] = aR.x; As[0][ak + 1][arow] = aR.y;
    As[0][ak + 2][arow] = aR.z; As[0][ak + 3][arow] = aR.w;
    *(float4*)&Bs[0][bkr][bn] = bR;
    __syncthreads();

    unsigned long long acc[8][4];
    #pragma unroll
    for (int r = 0; r < 8; r++)
        #pragma unroll
        for (int j = 0; j < 4; j++) acc[r][j] = 0ULL;

    int buf = 0;
    #pragma unroll 1
    for (int kt = 0; kt < KT; ++kt) {
        float4 aN, bN;
        if (kt + 1 < KT) {
            aN = *(const float4*)(Ag + (kt + 1) * 8);
            bN = bvalid ? *(const float4*)(Bg + (size_t)(kt + 1) * 8 * NDIM)
                        : make_float4(0.f, 0.f, 0.f, 0.f);
        }
        #pragma unroll
        for (int kk = 0; kk < 8; kk++) {
            float4 a0 = *(const float4*)&As[buf][kk][ty * 4];
            float4 a1 = *(const float4*)&As[buf][kk][64 + ty * 4];
            ulonglong2 b0 = *(const ulonglong2*)&Bs[buf][kk][tx * 4];
            ulonglong2 b1 = *(const ulonglong2*)&Bs[buf][kk][64 + tx * 4];
            unsigned long long bv0 = b0.x, bv1 = b0.y, bv2 = b1.x, bv3 = b1.y;
            float av[8] = {a0.x, a0.y, a0.z, a0.w, a1.x, a1.y, a1.z, a1.w};
            #pragma unroll
            for (int r = 0; r < 8; r++) {
                unsigned long long ad = dup2(av[r]);
                acc[r][0] = fma2(ad, bv0, acc[r][0]);
                acc[r][1] = fma2(ad, bv1, acc[r][1]);
                acc[r][2] = fma2(ad, bv2, acc[r][2]);
                acc[r][3] = fma2(ad, bv3, acc[r][3]);
            }
        }
        if (kt + 1 < KT) {
            int nb = buf ^ 1;
            As[nb][ak + 0][arow] = aN.x; As[nb][ak + 1][arow] = aN.y;
            As[nb][ak + 2][arow] = aN.z; As[nb][ak + 3][arow] = aN.w;
            *(float4*)&Bs[nb][bkr][bn] = bN;
            __syncthreads();
            buf = nb;
        }
    }

    // epilogue
    bool cval0 = true, cval1 = true;
    if (!FFN1) {
        cval0 = (n0 + tx * 4 + 4 <= NDIM);
        cval1 = (n0 + 64 + tx * 4 + 4 <= NDIM);
    }
    float4 bias0 = make_float4(0.f, 0.f, 0.f, 0.f);
    float4 bias1 = make_float4(0.f, 0.f, 0.f, 0.f);
    if (cval0) bias0 = *(const float4*)&bp[n0 + tx * 4];
    if (cval1) bias1 = *(const float4*)&bp[n0 + 64 + tx * 4];

    #pragma unroll
    for (int r = 0; r < 8; r++) {
        int row = m0 + ((r < 4) ? (ty * 4 + r) : (64 + ty * 4 + (r - 4)));
        float p0x, p0y, p1x, p1y, p2x, p2y, p3x, p3y;
        unpack2(acc[r][0], p0x, p0y);
        unpack2(acc[r][1], p1x, p1y);
        unpack2(acc[r][2], p2x, p2y);
        unpack2(acc[r][3], p3x, p3y);
        if (FFN1) {
            float4 v0 = make_float4(fmaxf(p0x + bias0.x, 0.f), fmaxf(p0y + bias0.y, 0.f),
                                    fmaxf(p1x + bias0.z, 0.f), fmaxf(p1y + bias0.w, 0.f));
            float4 v1 = make_float4(fmaxf(p2x + bias1.x, 0.f), fmaxf(p2y + bias1.y, 0.f),
                                    fmaxf(p3x + bias1.z, 0.f), fmaxf(p3y + bias1.w, 0.f));
            *(float4*)&Cout[(size_t)row * NDIM + n0 + tx * 4] = v0;
            *(float4*)&Cout[(size_t)row * NDIM + n0 + 64 + tx * 4] = v1;
        } else {
            if (cval0) {
                float* cp = &Cout[(size_t)row * NDIM + n0 + tx * 4];
                float4 old = *(const float4*)cp;
                *(float4*)cp = make_float4(old.x + p0x + bias0.x, old.y + p0y + bias0.y,
                                           old.z + p1x + bias0.z, old.w + p1y + bias0.w);
            }
            if (cval1) {
                float* cp = &Cout[(size_t)row * NDIM + n0 + 64 + tx * 4];
                float4 old = *(const float4*)cp;
                *(float4*)cp = make_float4(old.x + p2x + bias1.x, old.y + p2y + bias1.y,
                                           old.z + p3x + bias1.z, old.w + p3y + bias1.w);
            }
        }
    }
}

// ------------------------- head + denorm + transpose ----------------
__global__ void head_kernel(const float* __restrict__ Wh,
                            const float* __restrict__ bh,
                            const float* __restrict__ rev_w,
                            const float* __restrict__ rev_b,
                            float* __restrict__ out) {
    int prow = blockIdx.x;
    int c = g_chan[prow];
    if (c < 0) return;
    int kc = g_clusprow[prow];

    __shared__ __align__(16) float Zs[32][65];
    __shared__ __align__(16) float Ws[64][96];

    int tid = threadIdx.x;       // 256
    int row = tid & 31;          // batch index b
    int cg  = tid >> 5;          // 8 column groups of 12
    float acc[12];
    #pragma unroll
    for (int j = 0; j < 12; j++) acc[j] = 0.f;

    const float* Whk = Wh + (size_t)kc * L_ * O_;
    for (int l0 = 0; l0 < L_; l0 += 64) {
        int lc = min(64, L_ - l0);
        for (int i = tid; i < 32 * 64; i += 256) {
            int rr = i >> 6, ll = i & 63;
            Zs[rr][ll] = (ll < lc) ? g_Z[(size_t)(prow * 32 + rr) * L_ + l0 + ll] : 0.f;
        }
        for (int i = tid; i < 64 * 96; i += 256) {
            int ll = i / 96, o = i - ll * 96;
            Ws[ll][o] = (ll < lc) ? Whk[(size_t)(l0 + ll) * O_ + o] : 0.f;
        }
        __syncthreads();
        #pragma unroll 8
        for (int ll = 0; ll < 64; ll++) {
            float a = Zs[row][ll];
            float4 w0 = *(const float4*)&Ws[ll][cg * 12];
            float4 w1 = *(const float4*)&Ws[ll][cg * 12 + 4];
            float4 w2 = *(const float4*)&Ws[ll][cg * 12 + 8];
            acc[0]  += a * w0.x; acc[1]  += a * w0.y; acc[2]  += a * w0.z; acc[3]  += a * w0.w;
            acc[4]  += a * w1.x; acc[5]  += a * w1.y; acc[6]  += a * w1.z; acc[7]  += a * w1.w;
            acc[8]  += a * w2.x; acc[9]  += a * w2.y; acc[10] += a * w2.z; acc[11] += a * w2.w;
        }
        __syncthreads();
    }

    int rg = prow * 32 + row;
    float mean = g_mean[rg], stdv = g_std[rg];
    float w = rev_w[c], rb = rev_b[c];
    float scale = stdv / w;
    #pragma unroll
    for (int j = 0; j < 12; j++) {
        int o = cg * 12 + j;
        float y = acc[j] + bh[kc * O_ + o];
        out[((size_t)row * O_ + o) * C_ + c] = (y - rb) * scale + mean;
    }
}

// ------------------------- launch ----------------------------------
extern "C" void kernel_launch(void* const* d_in, const int* in_sizes, int n_in,
                              void* d_out, int out_size) {
    const float* x     = (const float*)d_in[0];
    const float* rev_w = (const float*)d_in[1];
    const float* rev_b = (const float*)d_in[2];
    const float* W1    = (const float*)d_in[3];
    const float* b1    = (const float*)d_in[4];
    const float* W2    = (const float*)d_in[5];
    const float* b2    = (const float*)d_in[6];
    const float* Wh    = (const float*)d_in[7];
    const float* bh    = (const float*)d_in[8];
    const int*   assign = (const int*)d_in[9];
    float* out = (float*)d_out;

    prep_kernel<<<1, 256>>>(assign);
    revin_kernel<<<MTOT, 128>>>(x, rev_w, rev_b);
    for (int l = 0; l < NL_; l++) {
        ffn_gemm<true ><<<dim3(DFF_ / 128, NGRP), 256>>>(W1, b1, l);
        ffn_gemm<false><<<dim3((L_ + 127) / 128, NGRP), 256>>>(W2, b2, l);
    }
    head_kernel<<<PROWS, 256>>>(Wh, bh, rev_w, rev_b, out);
}